// round 6
// baseline (speedup 1.0000x reference)
#include <cuda_runtime.h>
#include <cuda_bf16.h>

// Problem constants
#define S 8192
#define D 1024
#define E 64
#define CAP 128
#define SHIFT 4096
#define RANK_Y 8
static const long long SEC = (long long)S * E * CAP;   // 67108864

#define GEMM_BLOCKS 128
#define FILL_BLOCKS 1024
// out_size = 1 + 2*SEC + 64 + 1 = 134217794 floats; n4 = 33554448 float4 (+2 tail)
#define N4       33554448LL
#define Q16      2097153LL            // N4/16
#define A4       (13 * Q16)           // fill share in k1
#define B4       (2 * Q16)            // fill share in k_rank
// k_pospfx fills [A4+B4, N4)

// ---------------- scratch (device globals; no cross-call state) -------------
__device__ int   g_beste[S];
__device__ float g_gmax[S];
__device__ int   g_rank_part[RANK_Y * S];
__device__ int   g_expert_at_p[S];
__device__ int   g_token_at_p[S];
__device__ int   g_choff[S];                 // [128 chunks][64 experts] excl prefix
__device__ float g_me_part[GEMM_BLOCKS * E];
__device__ int   g_cnt_part[GEMM_BLOCKS * E];

// proven R2 fill pattern: grid-stride, plain float4 stores
__device__ __forceinline__ void fill_gs(float4* o4, long long lo, long long hi,
                                        long long slot, long long nslots) {
    const float4 z = make_float4(0.f, 0.f, 0.f, 0.f);
    for (long long i = lo + slot; i < hi; i += nslots) o4[i] = z;
}

// ---------------------------------------------------------------------------
// K1: blocks 0..127 : GEMM (64 tokens x 64 experts) + softmax epilogue
//     blocks 128..  : zero-fill [0, A4) float4s
// ---------------------------------------------------------------------------
__global__ void k1_fused(const float* __restrict__ x,
                         const float* __restrict__ w,
                         float* __restrict__ out) {
    const int tid = threadIdx.x;

    if (blockIdx.x < GEMM_BLOCKS) {
        __shared__ float sbuf[64 * 65];           // As/Bs alias + logits L[64][65]
        float (*As)[64] = (float(*)[64])sbuf;          // [32][64]
        float (*Bs)[64] = (float(*)[64])(sbuf + 2048); // [32][64]
        __shared__ float smax[64], sinv[64];
        __shared__ int   scnt[E];

        const int m0 = blockIdx.x * 64;
        const int tx = tid & 15;
        const int ty = tid >> 4;
        float acc[4][4];
        #pragma unroll
        for (int i = 0; i < 4; i++)
            #pragma unroll
            for (int j = 0; j < 4; j++) acc[i][j] = 0.0f;

        for (int k0 = 0; k0 < D; k0 += 32) {
            #pragma unroll
            for (int r = 0; r < 8; r++) {
                int l  = tid + r * 256;
                int mm = l & 63;
                int kk = l >> 6;
                As[kk][mm] = x[(long long)(m0 + mm) * D + k0 + kk];
                Bs[kk][mm] = w[(long long)mm * D + k0 + kk];
            }
            __syncthreads();
            #pragma unroll
            for (int kk = 0; kk < 32; kk++) {
                const float4 a = *(const float4*)(&As[kk][ty * 4]);
                const float4 b = *(const float4*)(&Bs[kk][tx * 4]);
                float av[4] = {a.x, a.y, a.z, a.w};
                float bv[4] = {b.x, b.y, b.z, b.w};
                #pragma unroll
                for (int i = 0; i < 4; i++)
                    #pragma unroll
                    for (int j = 0; j < 4; j++)
                        acc[i][j] += av[i] * bv[j];
            }
            __syncthreads();
        }

        float* L = sbuf;                           // [64][65] padded
        #pragma unroll
        for (int i = 0; i < 4; i++)
            #pragma unroll
            for (int j = 0; j < 4; j++)
                L[(ty * 4 + i) * 65 + tx * 4 + j] = acc[i][j];
        if (tid < E) scnt[tid] = 0;
        __syncthreads();

        if (tid < 64) {
            const int t = tid;
            float bv = L[t * 65];
            int   bi = 0;
            #pragma unroll 8
            for (int e = 1; e < E; e++) {
                float v = L[t * 65 + e];
                if (v > bv) { bv = v; bi = e; }
            }
            float s = 0.0f;
            #pragma unroll 8
            for (int e = 0; e < E; e++) s += expf(L[t * 65 + e] - bv);
            float inv = 1.0f / s;
            smax[t] = bv;
            sinv[t] = inv;
            g_beste[m0 + t] = bi;
            g_gmax[m0 + t]  = inv;                 // max gate = 1/sum
            atomicAdd(&scnt[bi], 1);
        }
        __syncthreads();
        if (tid < E) {
            const int e = tid;
            float me = 0.0f;
            #pragma unroll 8
            for (int t = 0; t < 64; t++)
                me += expf(L[t * 65 + e] - smax[t]) * sinv[t];
            g_me_part[blockIdx.x * E + e]  = me;
            g_cnt_part[blockIdx.x * E + e] = scnt[e];
        }
    } else {
        long long slot = (long long)(blockIdx.x - GEMM_BLOCKS) * 256 + tid;
        fill_gs((float4*)out, 0, A4, slot, (long long)FILL_BLOCKS * 256);
        if (blockIdx.x == GEMM_BLOCKS && tid < 2)
            out[N4 * 4 + tid] = 0.0f;              // 2 tail floats
    }
}

// ---------------------------------------------------------------------------
// K2: blocks 0..255: rank by counting (partitioned). blocks 256..: fill B4.
// ---------------------------------------------------------------------------
__global__ void k_rank(float* __restrict__ out) {
    if (blockIdx.x < 256) {
        __shared__ float sh[1024];
        const int xb = blockIdx.x & 31;
        const int y  = blockIdx.x >> 5;
        const int t = xb * 256 + threadIdx.x;
        const int ubase = y * 1024;
        for (int i = threadIdx.x; i < 1024; i += 256) sh[i] = g_gmax[ubase + i];
        __syncthreads();
        const float g = g_gmax[t];
        int lo = t - ubase;
        if (lo < 0) lo = 0;
        if (lo > 1024) lo = 1024;
        int cnt = 0;
        for (int j = 0; j < lo; j++)    cnt += (sh[j] >= g);
        for (int j = lo; j < 1024; j++) cnt += (sh[j] >  g);
        g_rank_part[y * S + t] = cnt;
    } else {
        long long slot = (long long)(blockIdx.x - 256) * 256 + threadIdx.x;
        fill_gs((float4*)out, A4, A4 + B4, slot, (long long)FILL_BLOCKS * 256);
    }
}

// ---------------------------------------------------------------------------
// K3: block 0: position/roll + smem histogram + per-expert prefix.
//     blocks 1..: fill the final 1/16.
// ---------------------------------------------------------------------------
__global__ void k_pospfx(float* __restrict__ out) {
    const int tid = threadIdx.x;
    if (blockIdx.x == 0) {
        __shared__ int hist[128 * E];                 // 32 KB
        for (int i = tid; i < 128 * E; i += 1024) hist[i] = 0;
        __syncthreads();
        #pragma unroll
        for (int k = 0; k < 8; k++) {
            const int t = tid + k * 1024;
            int r = 0;
            #pragma unroll
            for (int y = 0; y < RANK_Y; y++) r += g_rank_part[y * S + t];
            const int p = (r + SHIFT) & (S - 1);
            const int e = g_beste[t];
            g_expert_at_p[p] = e;
            g_token_at_p[p]  = t;
            atomicAdd(&hist[(p >> 6) * E + e], 1);
        }
        __syncthreads();
        if (tid < E) {
            int run = 0;
            #pragma unroll 1
            for (int b = 0; b < 128; b++) {
                g_choff[b * E + tid] = run;
                run += hist[b * E + tid];
            }
        }
    } else {
        long long slot = (long long)(blockIdx.x - 1) * 1024 + tid;
        fill_gs((float4*)out, A4 + B4, N4, slot, (long long)FILL_BLOCKS * 1024);
    }
}

// ---------------------------------------------------------------------------
// K4: reduce partials -> l_aux, exp_counts, unrouted (no fill dependency)
// ---------------------------------------------------------------------------
__global__ void k_finalize(float* __restrict__ out) {
    __shared__ float red[E];
    __shared__ int   sc[E];
    const int e = threadIdx.x;
    float me = 0.0f;
    int   c  = 0;
    #pragma unroll 8
    for (int b = 0; b < GEMM_BLOCKS; b++) {
        me += g_me_part[b * E + e];
        c  += g_cnt_part[b * E + e];
    }
    const float inv = 1.0f / (float)S;
    red[e] = (me * inv) * ((float)c * inv);
    sc[e]  = c;
    out[1LL + 2LL * SEC + e] = (float)c;
    __syncthreads();
    if (e == 0) {
        float sum = 0.0f;
        int dropped = 0;
        for (int k = 0; k < E; k++) {
            sum += red[k];
            int d = sc[k] - CAP;
            if (d > 0) dropped += d;
        }
        out[0] = sum * (float)E * 0.01f;
        out[1LL + 2LL * SEC + E] = (float)dropped * inv;
    }
}

// ---------------------------------------------------------------------------
// K5: per-chunk within-chunk rank + sparse scatter (after all fill done)
// ---------------------------------------------------------------------------
__global__ void k_scatter(float* __restrict__ out) {
    __shared__ int se[64];
    const int i = threadIdx.x;
    const int p = blockIdx.x * 64 + i;
    const int e = g_expert_at_p[p];
    const int t = g_token_at_p[p];
    se[i] = e;
    __syncthreads();
    int c = 0;
    for (int j = 0; j < i; j++) c += (se[j] == e);
    const int loc = g_choff[blockIdx.x * E + e] + c;
    if (loc < CAP) {
        long long base = 1LL + ((long long)t * E + e) * CAP + loc;
        out[base]       = g_gmax[t];  // combine_weights
        out[base + SEC] = 1.0f;       // dispatch_mask
    }
}

// ---------------------------------------------------------------------------
extern "C" void kernel_launch(void* const* d_in, const int* in_sizes, int n_in,
                              void* d_out, int out_size) {
    const float* x = (const float*)d_in[0];   // [S, D]
    const float* w = (const float*)d_in[1];   // [E, D]
    float* out = (float*)d_out;

    k1_fused<<<GEMM_BLOCKS + FILL_BLOCKS, 256>>>(x, w, out);  // launch 0
    k_rank<<<256 + FILL_BLOCKS, 256>>>(out);                  // launch 1
    k_pospfx<<<1 + FILL_BLOCKS, 1024>>>(out);                 // launch 2
    k_finalize<<<1, E>>>(out);                                // launch 3
    k_scatter<<<S / 64, 64>>>(out);                           // launch 4
}